// round 3
// baseline (speedup 1.0000x reference)
#include <cuda_runtime.h>
#include <cstdint>

// GenODE: z' = tanh(z W1^T + b1) W2^T + b2, N=8192 rows, D=64, H=128.
// Fixed-step classic RK4, one step per output interval (dt = 1/63).
// 4 threads per row ("quad"): sub-thread s in {0..3} owns z dims [16s,16s+16)
// and hidden dims [32s,32s+32). Warp = 8 rows, lane = s*8 + q (q = row-in-warp),
// so the 8 lanes sharing s read identical SMEM weight addresses (broadcast).
//
// SMEM weight layouts (floats), padded so the 4 distinct per-warp LDS.128
// addresses land in disjoint bank groups:
//   sW1[d][g][36]  (32 used): group offsets g*36 words -> banks 0/4/8/12
//   sW2[j][g][20]  (16 used): group offsets g*20 words -> banks 0/20/8/28

#define NROWS 8192
#define TPTS  64

#define SW1_OFS 0
#define SW2_OFS 9216          // 64*144
#define SB1_OFS 19456         // + 128*80
#define SB2_OFS 19600         // + 4*36
#define SMEM_FLOATS 19680     // + 4*20

__device__ __forceinline__ float tanh_fast(float x) {
    float e = __expf(2.0f * x);
    return __fdividef(e - 1.0f, e + 1.0f);
}

// y: this thread's 16-dim slice of the stage input (registers)
// k: this thread's 16-dim slice of f(y) (registers, output)
__device__ __forceinline__ void eval_f(
    const float* __restrict__ sW1, const float* __restrict__ sW2,
    const float* __restrict__ sb1, const float* __restrict__ sb2,
    int q, int s, const float* y, float* k)
{
    float h[32];
    {
        const float4* bv = (const float4*)(sb1 + s * 36);
        #pragma unroll
        for (int m = 0; m < 8; m++) {
            float4 b = bv[m];
            h[4*m+0] = b.x; h[4*m+1] = b.y; h[4*m+2] = b.z; h[4*m+3] = b.w;
        }
    }
    // h_j += sum_d W1[j,d] * y_d   (j in [32s, 32s+32))
    #pragma unroll 1
    for (int sp = 0; sp < 4; sp++) {
        int src = sp * 8 + q;
        #pragma unroll
        for (int dd = 0; dd < 16; dd++) {
            float zv = __shfl_sync(0xffffffffu, y[dd], src);
            const float4* w = (const float4*)(sW1 + (sp*16 + dd)*144 + s*36);
            #pragma unroll
            for (int m = 0; m < 8; m++) {
                float4 wv = w[m];
                h[4*m+0] = fmaf(wv.x, zv, h[4*m+0]);
                h[4*m+1] = fmaf(wv.y, zv, h[4*m+1]);
                h[4*m+2] = fmaf(wv.z, zv, h[4*m+2]);
                h[4*m+3] = fmaf(wv.w, zv, h[4*m+3]);
            }
        }
    }
    #pragma unroll
    for (int i = 0; i < 32; i++) h[i] = tanh_fast(h[i]);

    {
        const float4* bv = (const float4*)(sb2 + s * 20);
        #pragma unroll
        for (int m = 0; m < 4; m++) {
            float4 b = bv[m];
            k[4*m+0] = b.x; k[4*m+1] = b.y; k[4*m+2] = b.z; k[4*m+3] = b.w;
        }
    }
    // k_d += sum_j W2[d,j] * h_j   (d in [16s, 16s+16))
    #pragma unroll 1
    for (int sp = 0; sp < 4; sp++) {
        int src = sp * 8 + q;
        #pragma unroll
        for (int jj = 0; jj < 32; jj++) {
            float hv = __shfl_sync(0xffffffffu, h[jj], src);
            const float4* w = (const float4*)(sW2 + (sp*32 + jj)*80 + s*20);
            #pragma unroll
            for (int m = 0; m < 4; m++) {
                float4 wv = w[m];
                k[4*m+0] = fmaf(wv.x, hv, k[4*m+0]);
                k[4*m+1] = fmaf(wv.y, hv, k[4*m+1]);
                k[4*m+2] = fmaf(wv.z, hv, k[4*m+2]);
                k[4*m+3] = fmaf(wv.w, hv, k[4*m+3]);
            }
        }
    }
}

__global__ void __launch_bounds__(256, 1)
ode_kernel(const float* __restrict__ rand_e,
           const float* __restrict__ z0_mean,
           const float* __restrict__ z0_log_sigma,
           const float* __restrict__ W1,
           const float* __restrict__ b1,
           const float* __restrict__ W2,
           const float* __restrict__ b2,
           float* __restrict__ out,
           long long z0_off, long long t_off, long long z_off)
{
    extern __shared__ float sm[];
    float* sW1 = sm + SW1_OFS;
    float* sW2 = sm + SW2_OFS;
    float* sb1 = sm + SB1_OFS;
    float* sb2 = sm + SB2_OFS;
    int tid = threadIdx.x;

    // W1: (H=128, D=64) row-major -> sW1[d][j>>5][j&31]
    for (int idx = tid; idx < 128 * 64; idx += 256) {
        int j = idx >> 6, d = idx & 63;
        sW1[d * 144 + (j >> 5) * 36 + (j & 31)] = W1[idx];
    }
    // W2: (D=64, H=128) row-major -> sW2[j][d>>4][d&15]
    for (int idx = tid; idx < 64 * 128; idx += 256) {
        int d = idx >> 7, j = idx & 127;
        sW2[j * 80 + (d >> 4) * 20 + (d & 15)] = W2[idx];
    }
    if (tid < 128)      sb1[(tid >> 5) * 36 + (tid & 31)] = b1[tid];
    else if (tid < 192) { int d = tid - 128; sb2[(d >> 4) * 20 + (d & 15)] = b2[d]; }
    __syncthreads();

    int lane = tid & 31;
    int q = lane & 7;
    int s = lane >> 3;
    int row = blockIdx.x * 64 + (tid >> 5) * 8 + q;

    if (t_off >= 0 && blockIdx.x == 0 && tid < TPTS)
        out[t_off + tid] = (float)tid * (1.0f / 63.0f);

    float sig = expf(z0_log_sigma[0]);
    float z[16];
    {
        const float4* rp = (const float4*)(rand_e + (size_t)row * 64 + s * 16);
        const float4* mp = (const float4*)(z0_mean + s * 16);
        #pragma unroll
        for (int m = 0; m < 4; m++) {
            float4 r = rp[m]; float4 zm = mp[m];
            z[4*m+0] = zm.x + sig * r.x;
            z[4*m+1] = zm.y + sig * r.y;
            z[4*m+2] = zm.z + sig * r.z;
            z[4*m+3] = zm.w + sig * r.w;
        }
    }

    size_t lofs = (size_t)row * 64 + s * 16;
    if (z0_off >= 0) {
        float4* p = (float4*)(out + z0_off + lofs);
        #pragma unroll
        for (int m = 0; m < 4; m++)
            p[m] = make_float4(z[4*m+0], z[4*m+1], z[4*m+2], z[4*m+3]);
    }
    {   // z at t=0 equals z0
        float4* p = (float4*)(out + z_off + lofs);
        #pragma unroll
        for (int m = 0; m < 4; m++)
            p[m] = make_float4(z[4*m+0], z[4*m+1], z[4*m+2], z[4*m+3]);
    }

    const float dt = 1.0f / 63.0f;
    #pragma unroll 1
    for (int step = 0; step < 63; step++) {
        float acc[16], y[16];
        #pragma unroll
        for (int i = 0; i < 16; i++) { y[i] = z[i]; acc[i] = 0.0f; }
        #pragma unroll 1
        for (int st = 0; st < 4; st++) {
            float k[16];
            eval_f(sW1, sW2, sb1, sb2, q, s, y, k);
            float bw = (st == 1 || st == 2) ? 2.0f : 1.0f;
            float aw = (st == 2) ? dt : ((st == 3) ? 0.0f : 0.5f * dt);
            #pragma unroll
            for (int i = 0; i < 16; i++) {
                acc[i] += bw * k[i];
                y[i]   = z[i] + aw * k[i];
            }
        }
        #pragma unroll
        for (int i = 0; i < 16; i++)
            z[i] += (dt * (1.0f / 6.0f)) * acc[i];

        float4* p = (float4*)(out + z_off + (size_t)(step + 1) * (NROWS * 64) + lofs);
        #pragma unroll
        for (int m = 0; m < 4; m++)
            p[m] = make_float4(z[4*m+0], z[4*m+1], z[4*m+2], z[4*m+3]);
    }
}

extern "C" void kernel_launch(void* const* d_in, const int* in_sizes, int n_in,
                              void* d_out, int out_size)
{
    const float* rand_e       = (const float*)d_in[0];
    const float* z0_mean      = (const float*)d_in[1];
    const float* z0_log_sigma = (const float*)d_in[2];
    const float* W1           = (const float*)d_in[3];
    const float* b1           = (const float*)d_in[4];
    const float* W2           = (const float*)d_in[5];
    const float* b2           = (const float*)d_in[6];

    const long long Z0SZ = (long long)NROWS * 64;   // 524288
    const long long TSZ  = TPTS;                    // 64
    const long long ZSZ  = (long long)TPTS * NROWS * 64;

    long long z0_off, t_off, z_off;
    long long osz = (long long)out_size;
    if (osz == Z0SZ + TSZ + ZSZ)      { z0_off = 0;  t_off = Z0SZ; z_off = Z0SZ + TSZ; }
    else if (osz == ZSZ)              { z0_off = -1; t_off = -1;   z_off = 0; }
    else if (osz == Z0SZ + ZSZ)       { z0_off = 0;  t_off = -1;   z_off = Z0SZ; }
    else                              { z0_off = 0;  t_off = Z0SZ; z_off = Z0SZ + TSZ; }

    cudaFuncSetAttribute(ode_kernel,
                         cudaFuncAttributeMaxDynamicSharedMemorySize,
                         SMEM_FLOATS * sizeof(float));

    ode_kernel<<<NROWS / 64, 256, SMEM_FLOATS * sizeof(float)>>>(
        rand_e, z0_mean, z0_log_sigma, W1, b1, W2, b2,
        (float*)d_out, z0_off, t_off, z_off);
}

// round 4
// speedup vs baseline: 1.3345x; 1.3345x over previous
#include <cuda_runtime.h>
#include <cstdint>

// GenODE: z' = tanh(z W1^T + b1) W2^T + b2, N=8192 rows, D=64, H=128.
// Fixed-step RK4, dt = 1/63, one step per output interval.
//
// R4 changes vs R3:
//  * 2 rows per thread (rA = wbase+q, rB = wbase+8+q): every SMEM weight
//    load (LDS.128) is reused for both rows -> LDS per FLOP halved.
//  * packed fma.rn.f32x2 along the OUTPUT dimension (j-pairs for h,
//    d-pairs for k). SMEM layouts already have outputs contiguous, so each
//    float4 weight load = 2 packed operands, no duplication. Broadcast
//    scalar is duplicated with one mov.b64 {x,x}. -> FMA issue slots halved
//    AND fp32 rate doubled (FFMA-3reg rt=2, FFMA2 does 2 FLOPs/slot).
//  * 128 threads/CTA (4 warps), 64 rows/CTA, grid=128. One warp per SMSP
//    saturates the FMA pipe at rt_SMSP=2.
//
// SMEM layouts (floats), padded so the 4 distinct per-warp LDS.128
// addresses land in disjoint bank groups:
//   sW1[d][g][36]  (32 used): j contiguous  -> packed h-pairs
//   sW2[j][g][20]  (16 used): d contiguous  -> packed k-pairs

#define NROWS 8192
#define TPTS  64

#define SW1_OFS 0
#define SW2_OFS 9216          // 64*144
#define SB1_OFS 19456         // + 128*80
#define SB2_OFS 19600         // + 4*36
#define SMEM_FLOATS 19680     // + 4*20

typedef unsigned long long ull;

__device__ __forceinline__ ull pack2(float a, float b) {
    ull r; asm("mov.b64 %0, {%1, %2};" : "=l"(r) : "f"(a), "f"(b)); return r;
}
__device__ __forceinline__ void unpack2(ull v, float& a, float& b) {
    asm("mov.b64 {%0, %1}, %2;" : "=f"(a), "=f"(b) : "l"(v));
}
__device__ __forceinline__ ull fma2(ull a, ull b, ull c) {
    ull d; asm("fma.rn.f32x2 %0, %1, %2, %3;" : "=l"(d) : "l"(a), "l"(b), "l"(c));
    return d;
}

__device__ __forceinline__ float tanh_fast(float x) {
    float e = __expf(2.0f * x);
    return __fdividef(e - 1.0f, e + 1.0f);
}

// yA/yB: 16-dim slices (dims [16s,16s+16)) of stage input for rows A and B.
// kA/kB: f(y) slices out.
__device__ __forceinline__ void eval2(
    const float* __restrict__ sW1, const float* __restrict__ sW2,
    const float* __restrict__ sb1, const float* __restrict__ sb2,
    int q, int s,
    const float* yA, const float* yB, float* kA, float* kB)
{
    // ---- h = b1 + W1 y, packed over j-pairs ----
    ull hA[16], hB[16];
    {
        const ull* bp = (const ull*)(sb1 + s * 36);
        #pragma unroll
        for (int p = 0; p < 16; p++) { hA[p] = bp[p]; hB[p] = bp[p]; }
    }
    #pragma unroll 1
    for (int sp = 0; sp < 4; sp++) {
        int src = sp * 8 + q;
        const float* rp = sW1 + sp * (16 * 144) + s * 36;
        #pragma unroll
        for (int dd = 0; dd < 16; dd++) {
            float zA = __shfl_sync(0xffffffffu, yA[dd], src);
            float zB = __shfl_sync(0xffffffffu, yB[dd], src);
            ull zzA = pack2(zA, zA);
            ull zzB = pack2(zB, zB);
            const ulonglong2* w = (const ulonglong2*)(rp + dd * 144);
            #pragma unroll
            for (int m = 0; m < 8; m++) {
                ulonglong2 wv = w[m];
                hA[2*m+0] = fma2(wv.x, zzA, hA[2*m+0]);
                hA[2*m+1] = fma2(wv.y, zzA, hA[2*m+1]);
                hB[2*m+0] = fma2(wv.x, zzB, hB[2*m+0]);
                hB[2*m+1] = fma2(wv.y, zzB, hB[2*m+1]);
            }
        }
    }

    // ---- tanh (scalar) ----
    float hAs[32], hBs[32];
    #pragma unroll
    for (int p = 0; p < 16; p++) {
        float a0, a1, b0, b1v;
        unpack2(hA[p], a0, a1);
        unpack2(hB[p], b0, b1v);
        hAs[2*p+0] = tanh_fast(a0);
        hAs[2*p+1] = tanh_fast(a1);
        hBs[2*p+0] = tanh_fast(b0);
        hBs[2*p+1] = tanh_fast(b1v);
    }

    // ---- k = b2 + W2 h, packed over d-pairs ----
    ull kAp[8], kBp[8];
    {
        const ull* bp = (const ull*)(sb2 + s * 20);
        #pragma unroll
        for (int p = 0; p < 8; p++) { kAp[p] = bp[p]; kBp[p] = bp[p]; }
    }
    #pragma unroll 1
    for (int sp = 0; sp < 4; sp++) {
        int src = sp * 8 + q;
        const float* rp = sW2 + sp * (32 * 80) + s * 20;
        #pragma unroll
        for (int jj = 0; jj < 32; jj++) {
            float ha = __shfl_sync(0xffffffffu, hAs[jj], src);
            float hb = __shfl_sync(0xffffffffu, hBs[jj], src);
            ull da = pack2(ha, ha);
            ull db = pack2(hb, hb);
            const ulonglong2* w = (const ulonglong2*)(rp + jj * 80);
            #pragma unroll
            for (int m = 0; m < 4; m++) {
                ulonglong2 wv = w[m];
                kAp[2*m+0] = fma2(wv.x, da, kAp[2*m+0]);
                kAp[2*m+1] = fma2(wv.y, da, kAp[2*m+1]);
                kBp[2*m+0] = fma2(wv.x, db, kBp[2*m+0]);
                kBp[2*m+1] = fma2(wv.y, db, kBp[2*m+1]);
            }
        }
    }
    #pragma unroll
    for (int p = 0; p < 8; p++) {
        unpack2(kAp[p], kA[2*p+0], kA[2*p+1]);
        unpack2(kBp[p], kB[2*p+0], kB[2*p+1]);
    }
}

__global__ void __launch_bounds__(128, 1)
ode_kernel(const float* __restrict__ rand_e,
           const float* __restrict__ z0_mean,
           const float* __restrict__ z0_log_sigma,
           const float* __restrict__ W1,
           const float* __restrict__ b1,
           const float* __restrict__ W2,
           const float* __restrict__ b2,
           float* __restrict__ out,
           long long z0_off, long long t_off, long long z_off)
{
    extern __shared__ float sm[];
    float* sW1 = sm + SW1_OFS;
    float* sW2 = sm + SW2_OFS;
    float* sb1 = sm + SB1_OFS;
    float* sb2 = sm + SB2_OFS;
    int tid = threadIdx.x;

    // W1: (H=128, D=64) row-major -> sW1[d][j>>5][j&31]
    for (int idx = tid; idx < 128 * 64; idx += 128) {
        int j = idx >> 6, d = idx & 63;
        sW1[d * 144 + (j >> 5) * 36 + (j & 31)] = W1[idx];
    }
    // W2: (D=64, H=128) row-major -> sW2[j][d>>4][d&15]
    for (int idx = tid; idx < 64 * 128; idx += 128) {
        int d = idx >> 7, j = idx & 127;
        sW2[j * 80 + (d >> 4) * 20 + (d & 15)] = W2[idx];
    }
    if (tid < 128) sb1[(tid >> 5) * 36 + (tid & 31)] = b1[tid];
    if (tid < 64)  sb2[(tid >> 4) * 20 + (tid & 15)] = b2[tid];
    __syncthreads();

    int lane = tid & 31;
    int q = lane & 7;        // row-pair slot within warp
    int s = lane >> 3;       // dim-slice: z dims [16s,16s+16), h dims [32s,32s+32)
    int wbase = blockIdx.x * 64 + (tid >> 5) * 16;
    int rowA = wbase + q;
    int rowB = wbase + 8 + q;

    if (t_off >= 0 && blockIdx.x == 0 && tid < TPTS)
        out[t_off + tid] = (float)tid * (1.0f / 63.0f);

    float sig = expf(z0_log_sigma[0]);
    float zA[16], zB[16];
    {
        const float4* rA = (const float4*)(rand_e + (size_t)rowA * 64 + s * 16);
        const float4* rB = (const float4*)(rand_e + (size_t)rowB * 64 + s * 16);
        const float4* mp = (const float4*)(z0_mean + s * 16);
        #pragma unroll
        for (int m = 0; m < 4; m++) {
            float4 ra = rA[m]; float4 rb = rB[m]; float4 zm = mp[m];
            zA[4*m+0] = zm.x + sig * ra.x; zA[4*m+1] = zm.y + sig * ra.y;
            zA[4*m+2] = zm.z + sig * ra.z; zA[4*m+3] = zm.w + sig * ra.w;
            zB[4*m+0] = zm.x + sig * rb.x; zB[4*m+1] = zm.y + sig * rb.y;
            zB[4*m+2] = zm.z + sig * rb.z; zB[4*m+3] = zm.w + sig * rb.w;
        }
    }

    size_t lofsA = (size_t)rowA * 64 + s * 16;
    size_t lofsB = (size_t)rowB * 64 + s * 16;
    if (z0_off >= 0) {
        float4* pA = (float4*)(out + z0_off + lofsA);
        float4* pB = (float4*)(out + z0_off + lofsB);
        #pragma unroll
        for (int m = 0; m < 4; m++) {
            pA[m] = make_float4(zA[4*m+0], zA[4*m+1], zA[4*m+2], zA[4*m+3]);
            pB[m] = make_float4(zB[4*m+0], zB[4*m+1], zB[4*m+2], zB[4*m+3]);
        }
    }
    {   // z at t=0 equals z0
        float4* pA = (float4*)(out + z_off + lofsA);
        float4* pB = (float4*)(out + z_off + lofsB);
        #pragma unroll
        for (int m = 0; m < 4; m++) {
            pA[m] = make_float4(zA[4*m+0], zA[4*m+1], zA[4*m+2], zA[4*m+3]);
            pB[m] = make_float4(zB[4*m+0], zB[4*m+1], zB[4*m+2], zB[4*m+3]);
        }
    }

    const float dt = 1.0f / 63.0f;
    #pragma unroll 1
    for (int step = 0; step < 63; step++) {
        float accA[16], accB[16], yA[16], yB[16];
        #pragma unroll
        for (int i = 0; i < 16; i++) {
            yA[i] = zA[i]; yB[i] = zB[i];
            accA[i] = 0.0f; accB[i] = 0.0f;
        }
        #pragma unroll 1
        for (int st = 0; st < 4; st++) {
            float kA[16], kB[16];
            eval2(sW1, sW2, sb1, sb2, q, s, yA, yB, kA, kB);
            float bw = (st == 1 || st == 2) ? 2.0f : 1.0f;
            float aw = (st == 2) ? dt : ((st == 3) ? 0.0f : 0.5f * dt);
            #pragma unroll
            for (int i = 0; i < 16; i++) {
                accA[i] += bw * kA[i];
                accB[i] += bw * kB[i];
                yA[i]   = zA[i] + aw * kA[i];
                yB[i]   = zB[i] + aw * kB[i];
            }
        }
        #pragma unroll
        for (int i = 0; i < 16; i++) {
            zA[i] += (dt * (1.0f / 6.0f)) * accA[i];
            zB[i] += (dt * (1.0f / 6.0f)) * accB[i];
        }

        size_t tofs = z_off + (size_t)(step + 1) * (NROWS * 64);
        float4* pA = (float4*)(out + tofs + lofsA);
        float4* pB = (float4*)(out + tofs + lofsB);
        #pragma unroll
        for (int m = 0; m < 4; m++) {
            pA[m] = make_float4(zA[4*m+0], zA[4*m+1], zA[4*m+2], zA[4*m+3]);
            pB[m] = make_float4(zB[4*m+0], zB[4*m+1], zB[4*m+2], zB[4*m+3]);
        }
    }
}

extern "C" void kernel_launch(void* const* d_in, const int* in_sizes, int n_in,
                              void* d_out, int out_size)
{
    const float* rand_e       = (const float*)d_in[0];
    const float* z0_mean      = (const float*)d_in[1];
    const float* z0_log_sigma = (const float*)d_in[2];
    const float* W1           = (const float*)d_in[3];
    const float* b1           = (const float*)d_in[4];
    const float* W2           = (const float*)d_in[5];
    const float* b2           = (const float*)d_in[6];

    const long long Z0SZ = (long long)NROWS * 64;   // 524288
    const long long TSZ  = TPTS;                    // 64
    const long long ZSZ  = (long long)TPTS * NROWS * 64;

    long long z0_off, t_off, z_off;
    long long osz = (long long)out_size;
    if (osz == Z0SZ + TSZ + ZSZ)      { z0_off = 0;  t_off = Z0SZ; z_off = Z0SZ + TSZ; }
    else if (osz == ZSZ)              { z0_off = -1; t_off = -1;   z_off = 0; }
    else if (osz == Z0SZ + ZSZ)       { z0_off = 0;  t_off = -1;   z_off = Z0SZ; }
    else                              { z0_off = 0;  t_off = Z0SZ; z_off = Z0SZ + TSZ; }

    cudaFuncSetAttribute(ode_kernel,
                         cudaFuncAttributeMaxDynamicSharedMemorySize,
                         SMEM_FLOATS * sizeof(float));

    ode_kernel<<<NROWS / 64, 128, SMEM_FLOATS * sizeof(float)>>>(
        rand_e, z0_mean, z0_log_sigma, W1, b1, W2, b2,
        (float*)d_out, z0_off, t_off, z_off);
}